// round 3
// baseline (speedup 1.0000x reference)
#include <cuda_runtime.h>
#include <cuda_bf16.h>
#include <math.h>

// Problem constants
#define BATCH 2
#define VIEWS 6
#define CH    256
#define NQ    900
#define H0    64
#define W0    176
#define H1    32
#define W1    88
#define HW0   (H0*W0)     // 11264
#define HW1   (H1*W1)     // 2816
#define NHEAD 8
#define HD    32

// ---------------------------------------------------------------------------
// Scratch: one pooled static device buffer (allocation-free per harness rules)
// ---------------------------------------------------------------------------
#define N_F0T ((size_t)BATCH*VIEWS*HW0*CH)   // 34,603,008
#define N_F1T ((size_t)BATCH*VIEWS*HW1*CH)   //  8,650,752
#define N_MAT ((size_t)BATCH*NQ*CH)          //    460,800
// layout: [f0t | f1t | ctx | qp | kp | vp | ao]
__device__ __align__(256) float g_pool[N_F0T + N_F1T + 5*N_MAT];

// ---------------------------------------------------------------------------
// 1) Transpose [C,HW] -> [HW,C] per (b,v)
// ---------------------------------------------------------------------------
__global__ __launch_bounds__(256)
void transpose_kernel(const float* __restrict__ in,
                      float* __restrict__ out, int HW) {
    __shared__ float tile[32][33];
    const int bv = blockIdx.z;
    const int p0 = blockIdx.x * 32;
    const int c0 = blockIdx.y * 32;
    const float* src = in  + (size_t)bv * CH * HW;
    float*       dst = out + (size_t)bv * HW * CH;
    const int tx = threadIdx.x, ty = threadIdx.y;
#pragma unroll
    for (int i = 0; i < 32; i += 8) {
        tile[ty + i][tx] = src[(size_t)(c0 + ty + i) * HW + (p0 + tx)];
    }
    __syncthreads();
#pragma unroll
    for (int i = 0; i < 32; i += 8) {
        dst[(size_t)(p0 + ty + i) * CH + (c0 + tx)] = tile[tx][ty + i];
    }
}

// ---------------------------------------------------------------------------
// 2) Sampler: one block per (b,q); thread = channel. Projection math done by
//    threads 0..23 (v*4+k) into smem; gather loop is block-uniform.
// ---------------------------------------------------------------------------
__global__ __launch_bounds__(256)
void sampler_kernel(const float* __restrict__ refs,
                    const float* __restrict__ intr,
                    const float* __restrict__ extr,
                    const float* __restrict__ f0t,
                    const float* __restrict__ f1t,
                    float* __restrict__ ctx) {
    const int b = blockIdx.x / NQ;
    const int q = blockIdx.x % NQ;
    const int c = threadIdx.x;

    __shared__ float sx[2][24], sy[2][24];
    __shared__ int   sval[24];

    if (c < 24) {
        const int v = c >> 2, k = c & 3;
        const float kx[4] = {0.f, 2.f, 0.f, -2.f};
        const float ky[4] = {0.f, 0.f, 2.f,  0.f};
        const float px = refs[((size_t)b*NQ + q)*3 + 0] + kx[k];
        const float py = refs[((size_t)b*NQ + q)*3 + 1] + ky[k];
        const float pz = refs[((size_t)b*NQ + q)*3 + 2];
        const float* E  = extr + (size_t)(b*VIEWS + v)*16;
        const float* Kk = intr + (size_t)(b*VIEWS + v)*9;
        const float c0 = E[0]*px + E[1]*py + E[2]*pz  + E[3];
        const float c1 = E[4]*px + E[5]*py + E[6]*pz  + E[7];
        const float c2 = E[8]*px + E[9]*py + E[10]*pz + E[11];
        const float uu = Kk[0]*c0 + Kk[1]*c1 + Kk[2]*c2;
        const float vv = Kk[3]*c0 + Kk[4]*c1 + Kk[5]*c2;
        const float zz = Kk[6]*c0 + Kk[7]*c1 + Kk[8]*c2;
        const float zs = (fabsf(zz) > 1e-6f) ? zz : 1e-6f;
        const float iu = uu / zs, iv = vv / zs;
        // level 0 (replicate reference grid round-trip exactly)
        {
            float gx = 2.f * iu / (float)(W0 - 1) - 1.f;
            float gy = 2.f * iv / (float)(H0 - 1) - 1.f;
            sx[0][c] = (gx + 1.f) * 0.5f * (float)(W0 - 1);
            sy[0][c] = (gy + 1.f) * 0.5f * (float)(H0 - 1);
        }
        // level 1
        {
            float gx = 2.f * iu / (float)(W1 - 1) - 1.f;
            float gy = 2.f * iv / (float)(H1 - 1) - 1.f;
            sx[1][c] = (gx + 1.f) * 0.5f * (float)(W1 - 1);
            sy[1][c] = (gy + 1.f) * 0.5f * (float)(H1 - 1);
        }
        sval[c] = (zz > 0.f) ? 1 : 0;
    }
    __syncthreads();

    float cnt = 0.f;
#pragma unroll
    for (int t = 0; t < 24; t++) cnt += (float)sval[t];
    cnt = fmaxf(cnt, 1.f);

    float acc = 0.f;
    for (int t = 0; t < 24; t++) {
        if (!sval[t]) continue;
        const int v = t >> 2;
#pragma unroll
        for (int l = 0; l < 2; l++) {
            const int W = l ? W1 : W0;
            const int H = l ? H1 : H0;
            const float* base = l ? (f1t + (size_t)(b*VIEWS + v)*HW1*CH)
                                  : (f0t + (size_t)(b*VIEWS + v)*HW0*CH);
            const float x = sx[l][t], y = sy[l][t];
            const float x0f = floorf(x), y0f = floorf(y);
            const float wx1 = x - x0f, wx0 = 1.f - wx1;
            const float wy1 = y - y0f, wy0 = 1.f - wy1;
#pragma unroll
            for (int dy = 0; dy < 2; dy++) {
#pragma unroll
                for (int dx = 0; dx < 2; dx++) {
                    const float xf = x0f + (float)dx;
                    const float yf = y0f + (float)dy;
                    if (xf >= 0.f && xf <= (float)(W - 1) &&
                        yf >= 0.f && yf <= (float)(H - 1)) {
                        const int xi = (int)xf, yi = (int)yf;
                        const float w = (dx ? wx1 : wx0) * (dy ? wy1 : wy0);
                        acc += w * base[((size_t)(yi * W + xi)) * CH + c];
                    }
                }
            }
        }
    }
    ctx[((size_t)b*NQ + q)*CH + c] = acc / (2.f * cnt);
}

// ---------------------------------------------------------------------------
// 3) GEMM (NT): C[m,n] = sum_k A[m,k]*B[n,k] + bias[n].  K == N == 256.
// ---------------------------------------------------------------------------
#define GBM 64
#define GBN 64
#define GBK 16
__global__ __launch_bounds__(256)
void gemm_nt_bias(const float* __restrict__ A,
                  const float* __restrict__ B,
                  const float* __restrict__ bias,
                  float* __restrict__ Cout, int M) {
    __shared__ float As[GBM][GBK + 1];
    __shared__ float Bs[GBN][GBK + 1];
    const int tid = threadIdx.y * 16 + threadIdx.x;
    const int m0 = blockIdx.y * GBM, n0 = blockIdx.x * GBN;
    const int lr = tid >> 2;         // 0..63
    const int lc = (tid & 3) * 4;    // 0,4,8,12
    float acc[4][4] = {};
    for (int k0 = 0; k0 < CH; k0 += GBK) {
        const int am = m0 + lr;
        float4 av = make_float4(0.f, 0.f, 0.f, 0.f);
        if (am < M) av = *(const float4*)(A + (size_t)am * CH + k0 + lc);
        As[lr][lc+0] = av.x; As[lr][lc+1] = av.y;
        As[lr][lc+2] = av.z; As[lr][lc+3] = av.w;
        float4 bv4 = *(const float4*)(B + (size_t)(n0 + lr) * CH + k0 + lc);
        Bs[lr][lc+0] = bv4.x; Bs[lr][lc+1] = bv4.y;
        Bs[lr][lc+2] = bv4.z; Bs[lr][lc+3] = bv4.w;
        __syncthreads();
#pragma unroll
        for (int kk = 0; kk < GBK; kk++) {
            float a[4], bb[4];
#pragma unroll
            for (int i = 0; i < 4; i++) a[i]  = As[threadIdx.y*4 + i][kk];
#pragma unroll
            for (int j = 0; j < 4; j++) bb[j] = Bs[threadIdx.x*4 + j][kk];
#pragma unroll
            for (int i = 0; i < 4; i++)
#pragma unroll
                for (int j = 0; j < 4; j++)
                    acc[i][j] = fmaf(a[i], bb[j], acc[i][j]);
        }
        __syncthreads();
    }
#pragma unroll
    for (int i = 0; i < 4; i++) {
        const int m = m0 + threadIdx.y*4 + i;
        if (m >= M) continue;
#pragma unroll
        for (int j = 0; j < 4; j++) {
            const int n = n0 + threadIdx.x*4 + j;
            Cout[(size_t)m * CH + n] = acc[i][j] + bias[n];
        }
    }
}

// ---------------------------------------------------------------------------
// 4) Attention: one thread per query, per (b,h). K/V tiles staged in smem.
//    Rare-branch online softmax: steady state = 64 FMA + 1 exp per key.
// ---------------------------------------------------------------------------
__global__ __launch_bounds__(128)
void attn_kernel(const float* __restrict__ Qp,
                 const float* __restrict__ Kp,
                 const float* __restrict__ Vp,
                 float* __restrict__ Out) {
    const int pair = blockIdx.x;
    const int b = pair >> 3, h = pair & 7;
    const int tid = threadIdx.x;
    const int qi = blockIdx.y * 128 + tid;
    const bool active = (qi < NQ);

    __shared__ float ks[64][32];
    __shared__ float vs[64][32];

    float qv[HD];
    if (active) {
        const float* qp = Qp + ((size_t)b*NQ + qi)*CH + h*HD;
#pragma unroll
        for (int d = 0; d < HD; d++) qv[d] = qp[d] * 0.1767766953f; // 1/sqrt(32)
    }
    float m = -1e30f, l = 0.f, o[HD];
#pragma unroll
    for (int d = 0; d < HD; d++) o[d] = 0.f;

    for (int kt = 0; kt < NQ; kt += 64) {
        const int cnt = min(64, NQ - kt);
        __syncthreads();
        for (int idx = tid; idx < 64*32; idx += 128) {
            const int r = idx >> 5, d = idx & 31;
            float kk = 0.f, vv = 0.f;
            if (r < cnt) {
                const size_t off = ((size_t)b*NQ + kt + r)*CH + h*HD + d;
                kk = Kp[off]; vv = Vp[off];
            }
            ks[r][d] = kk; vs[r][d] = vv;
        }
        __syncthreads();
        if (active) {
            for (int j = 0; j < cnt; j++) {
                float s0 = 0.f, s1 = 0.f, s2 = 0.f, s3 = 0.f;
#pragma unroll
                for (int d = 0; d < HD; d += 4) {
                    s0 = fmaf(qv[d+0], ks[j][d+0], s0);
                    s1 = fmaf(qv[d+1], ks[j][d+1], s1);
                    s2 = fmaf(qv[d+2], ks[j][d+2], s2);
                    s3 = fmaf(qv[d+3], ks[j][d+3], s3);
                }
                const float s = (s0 + s1) + (s2 + s3);
                if (s > m) {
                    const float r = __expf(m - s);
                    l = l * r + 1.f;
#pragma unroll
                    for (int d = 0; d < HD; d++) o[d] = fmaf(o[d], r, vs[j][d]);
                    m = s;
                } else {
                    const float p = __expf(s - m);
                    l += p;
#pragma unroll
                    for (int d = 0; d < HD; d++) o[d] = fmaf(p, vs[j][d], o[d]);
                }
            }
        }
    }
    if (active) {
        const float inv = 1.f / l;
        float* op = Out + ((size_t)b*NQ + qi)*CH + h*HD;
#pragma unroll
        for (int d = 0; d < HD; d++) op[d] = o[d] * inv;
    }
}

// ---------------------------------------------------------------------------
// Launch
// ---------------------------------------------------------------------------
extern "C" void kernel_launch(void* const* d_in, const int* in_sizes, int n_in,
                              void* d_out, int out_size) {
    (void)in_sizes; (void)n_in; (void)out_size;
    const float* f0   = (const float*)d_in[0];
    const float* f1   = (const float*)d_in[1];
    const float* refs = (const float*)d_in[2];
    const float* intr = (const float*)d_in[3];
    const float* extr = (const float*)d_in[4];
    const float* qin  = (const float*)d_in[5];
    const float* Wq = (const float*)d_in[6];  const float* bq = (const float*)d_in[7];
    const float* Wk = (const float*)d_in[8];  const float* bk = (const float*)d_in[9];
    const float* Wv = (const float*)d_in[10]; const float* bv = (const float*)d_in[11];
    const float* Wo = (const float*)d_in[12]; const float* bo = (const float*)d_in[13];

    float* pool;
    cudaGetSymbolAddress((void**)&pool, g_pool);
    float* pf0t = pool;
    float* pf1t = pf0t + N_F0T;
    float* pctx = pf1t + N_F1T;
    float* pq   = pctx + N_MAT;
    float* pk   = pq   + N_MAT;
    float* pv   = pk   + N_MAT;
    float* pao  = pv   + N_MAT;

    // 1) channel-last transpose of both feature levels
    transpose_kernel<<<dim3(HW0/32, CH/32, BATCH*VIEWS), dim3(32, 8)>>>(f0, pf0t, HW0);
    transpose_kernel<<<dim3(HW1/32, CH/32, BATCH*VIEWS), dim3(32, 8)>>>(f1, pf1t, HW1);

    // 2) multi-view sampler -> ctx [B,Q,C]
    sampler_kernel<<<BATCH*NQ, CH>>>(refs, intr, extr, pf0t, pf1t, pctx);

    // 3) Q/K/V projections
    const int M = BATCH * NQ;                       // 1800
    dim3 ggrid(CH/GBN, (M + GBM - 1)/GBM), gblk(16, 16);
    gemm_nt_bias<<<ggrid, gblk>>>(qin,  Wq, bq, pq, M);
    gemm_nt_bias<<<ggrid, gblk>>>(pctx, Wk, bk, pk, M);
    gemm_nt_bias<<<ggrid, gblk>>>(pctx, Wv, bv, pv, M);

    // 4) attention
    attn_kernel<<<dim3(BATCH*NHEAD, (NQ + 127)/128), 128>>>(pq, pk, pv, pao);

    // 5) output projection -> d_out
    gemm_nt_bias<<<ggrid, gblk>>>(pao, Wo, bo, (float*)d_out, M);
}

// round 8
// speedup vs baseline: 1.0831x; 1.0831x over previous
#include <cuda_runtime.h>
#include <cuda_fp16.h>
#include <math.h>

// Problem constants
#define BATCH 2
#define VIEWS 6
#define CH    256
#define NQ    900
#define H0    64
#define W0    176
#define H1    32
#define W1    88
#define HW0   (H0*W0)     // 11264
#define HW1   (H1*W1)     // 2816
#define NHEAD 8
#define HD    32

typedef unsigned long long ull;

// packed f32x2 helpers (FFMA2 — only reachable via PTX fma.rn.f32x2)
__device__ __forceinline__ ull pack2(float lo, float hi) {
    ull r; asm("mov.b64 %0,{%1,%2};" : "=l"(r) : "f"(lo), "f"(hi)); return r;
}
__device__ __forceinline__ void unpack2(ull v, float& lo, float& hi) {
    asm("mov.b64 {%0,%1},%2;" : "=f"(lo), "=f"(hi) : "l"(v));
}
__device__ __forceinline__ ull fma2(ull a, ull b, ull c) {
    ull d; asm("fma.rn.f32x2 %0,%1,%2,%3;" : "=l"(d) : "l"(a), "l"(b), "l"(c)); return d;
}

// ---------------------------------------------------------------------------
// Scratch (static device globals; allocation-free per harness rules)
// ---------------------------------------------------------------------------
#define N_F0T ((size_t)BATCH*VIEWS*HW0*CH)   // 34,603,008
#define N_F1T ((size_t)BATCH*VIEWS*HW1*CH)   //  8,650,752
#define N_MAT ((size_t)BATCH*NQ*CH)          //    460,800
__device__ __align__(256) __half g_feat[N_F0T + N_F1T];   // fp16 channel-last features
__device__ __align__(256) float  g_mats[5*N_MAT];         // ctx | q | k | v | ao

// ---------------------------------------------------------------------------
// 1) Transpose [C,HW] -> [HW,C] per (b,v), fp32 -> fp16
// ---------------------------------------------------------------------------
__global__ __launch_bounds__(256)
void transpose_f16(const float* __restrict__ in, __half* __restrict__ out, int HW) {
    __shared__ float tile[32][33];      // [c][p]
    const int bv = blockIdx.z;
    const int p0 = blockIdx.x * 32;
    const int c0 = blockIdx.y * 32;
    const float* src = in  + (size_t)bv * CH * HW;
    __half*      dst = out + (size_t)bv * HW * CH;
    const int tx = threadIdx.x, ty = threadIdx.y;   // 32 x 8
#pragma unroll
    for (int i = 0; i < 32; i += 8)
        tile[ty + i][tx] = src[(size_t)(c0 + ty + i) * HW + (p0 + tx)];
    __syncthreads();
    const int tid = ty * 32 + tx;
#pragma unroll
    for (int i = 0; i < 2; i++) {
        const int idx = tid + i * 256;       // 0..511
        const int p = idx >> 4, c2 = idx & 15;
        __half2 h = __floats2half2_rn(tile[2*c2][p], tile[2*c2 + 1][p]);
        *(__half2*)(dst + (size_t)(p0 + p) * CH + c0 + 2*c2) = h;
    }
}

// ---------------------------------------------------------------------------
// 2) Sampler: one block per (b,q); 128 threads, 2 channels per thread (half2).
// ---------------------------------------------------------------------------
__global__ __launch_bounds__(128)
void sampler_kernel(const float* __restrict__ refs,
                    const float* __restrict__ intr,
                    const float* __restrict__ extr,
                    const __half* __restrict__ f0t,
                    const __half* __restrict__ f1t,
                    float* __restrict__ ctx) {
    const int b = blockIdx.x / NQ;
    const int q = blockIdx.x % NQ;
    const int t = threadIdx.x;           // channel pair 0..127

    __shared__ float sx[2][24], sy[2][24];
    __shared__ int   sval[24];

    if (t < 24) {
        const int v = t >> 2, k = t & 3;
        const float kx[4] = {0.f, 2.f, 0.f, -2.f};
        const float ky[4] = {0.f, 0.f, 2.f,  0.f};
        const float px = refs[((size_t)b*NQ + q)*3 + 0] + kx[k];
        const float py = refs[((size_t)b*NQ + q)*3 + 1] + ky[k];
        const float pz = refs[((size_t)b*NQ + q)*3 + 2];
        const float* E  = extr + (size_t)(b*VIEWS + v)*16;
        const float* Kk = intr + (size_t)(b*VIEWS + v)*9;
        const float c0 = E[0]*px + E[1]*py + E[2]*pz  + E[3];
        const float c1 = E[4]*px + E[5]*py + E[6]*pz  + E[7];
        const float c2 = E[8]*px + E[9]*py + E[10]*pz + E[11];
        const float uu = Kk[0]*c0 + Kk[1]*c1 + Kk[2]*c2;
        const float vv = Kk[3]*c0 + Kk[4]*c1 + Kk[5]*c2;
        const float zz = Kk[6]*c0 + Kk[7]*c1 + Kk[8]*c2;
        const float zs = (fabsf(zz) > 1e-6f) ? zz : 1e-6f;
        const float iu = uu / zs, iv = vv / zs;
        {   // replicate reference grid round-trip exactly
            float gx = 2.f * iu / (float)(W0 - 1) - 1.f;
            float gy = 2.f * iv / (float)(H0 - 1) - 1.f;
            sx[0][t] = (gx + 1.f) * 0.5f * (float)(W0 - 1);
            sy[0][t] = (gy + 1.f) * 0.5f * (float)(H0 - 1);
        }
        {
            float gx = 2.f * iu / (float)(W1 - 1) - 1.f;
            float gy = 2.f * iv / (float)(H1 - 1) - 1.f;
            sx[1][t] = (gx + 1.f) * 0.5f * (float)(W1 - 1);
            sy[1][t] = (gy + 1.f) * 0.5f * (float)(H1 - 1);
        }
        sval[t] = (zz > 0.f) ? 1 : 0;
    }
    __syncthreads();

    float cnt = 0.f;
#pragma unroll
    for (int i = 0; i < 24; i++) cnt += (float)sval[i];
    cnt = fmaxf(cnt, 1.f);

    float ax = 0.f, ay = 0.f;
    for (int i = 0; i < 24; i++) {
        if (!sval[i]) continue;
        const int v = i >> 2;
#pragma unroll
        for (int l = 0; l < 2; l++) {
            const int W = l ? W1 : W0;
            const int H = l ? H1 : H0;
            const __half2* base2 = (const __half2*)(l
                ? (f1t + (size_t)(b*VIEWS + v)*HW1*CH)
                : (f0t + (size_t)(b*VIEWS + v)*HW0*CH));
            const float x = sx[l][i], y = sy[l][i];
            const float x0f = floorf(x), y0f = floorf(y);
            const float wx1 = x - x0f, wx0 = 1.f - wx1;
            const float wy1 = y - y0f, wy0 = 1.f - wy1;
#pragma unroll
            for (int dy = 0; dy < 2; dy++) {
#pragma unroll
                for (int dx = 0; dx < 2; dx++) {
                    const float xf = x0f + (float)dx;
                    const float yf = y0f + (float)dy;
                    if (xf >= 0.f && xf <= (float)(W - 1) &&
                        yf >= 0.f && yf <= (float)(H - 1)) {
                        const int xi = (int)xf, yi = (int)yf;
                        const float w = (dx ? wx1 : wx0) * (dy ? wy1 : wy0);
                        float2 f = __half22float2(base2[(size_t)(yi * W + xi)*(CH/2) + t]);
                        ax = fmaf(w, f.x, ax);
                        ay = fmaf(w, f.y, ay);
                    }
                }
            }
        }
    }
    const float inv = 1.f / (2.f * cnt);
    float2 outv = make_float2(ax * inv, ay * inv);
    *(float2*)(ctx + ((size_t)b*NQ + q)*CH + 2*t) = outv;
}

// ---------------------------------------------------------------------------
// 3) GEMM (NT) with z-batching + packed f32x2 inner product.
//    C[m,n] = sum_k A[m,k]*B[n,k] + bias[n].  K == N == 256.
// ---------------------------------------------------------------------------
#define GBM 64
#define GBN 64
#define GBK 16
__global__ __launch_bounds__(256)
void gemm_nt3(const float* __restrict__ A0, const float* __restrict__ A1, const float* __restrict__ A2,
              const float* __restrict__ W0p, const float* __restrict__ W1p, const float* __restrict__ W2p,
              const float* __restrict__ b0, const float* __restrict__ b1, const float* __restrict__ b2,
              float* __restrict__ C0, float* __restrict__ C1, float* __restrict__ C2, int M) {
    const int z = blockIdx.z;
    const float* A    = (z == 0) ? A0 : (z == 1) ? A1 : A2;
    const float* Wt   = (z == 0) ? W0p : (z == 1) ? W1p : W2p;
    const float* bias = (z == 0) ? b0 : (z == 1) ? b1 : b2;
    float*       C    = (z == 0) ? C0 : (z == 1) ? C1 : C2;

    __shared__ float As[GBM][GBK + 1];   // [m][k]
    __shared__ float Bs[GBK][GBN + 2];   // [k][n]
    const int tid = threadIdx.x;
    const int m0 = blockIdx.y * GBM, n0 = blockIdx.x * GBN;
    const int lr = tid >> 2;           // 0..63
    const int lc = (tid & 3) * 4;      // 0,4,8,12
    const int ry = tid >> 4;           // 0..15 (m sub-tile)
    const int rx = tid & 15;           // 0..15 (n sub-tile)

    ull acc2[4][2];
#pragma unroll
    for (int i = 0; i < 4; i++) { acc2[i][0] = 0ull; acc2[i][1] = 0ull; }

    for (int k0 = 0; k0 < CH; k0 += GBK) {
        const int am = m0 + lr;
        float4 av = make_float4(0.f, 0.f, 0.f, 0.f);
        if (am < M) av = *(const float4*)(A + (size_t)am * CH + k0 + lc);
        As[lr][lc+0] = av.x; As[lr][lc+1] = av.y;
        As[lr][lc+2] = av.z; As[lr][lc+3] = av.w;
        float4 wv = *(const float4*)(Wt + (size_t)(n0 + lr) * CH + k0 + lc);
        Bs[lc+0][lr] = wv.x; Bs[lc+1][lr] = wv.y;
        Bs[lc+2][lr] = wv.z; Bs[lc+3][lr] = wv.w;
        __syncthreads();
#pragma unroll
        for (int kk = 0; kk < GBK; kk++) {
            const ull bb0 = *(const ull*)&Bs[kk][rx*4];
            const ull bb1 = *(const ull*)&Bs[kk][rx*4 + 2];
#pragma unroll
            for (int i = 0; i < 4; i++) {
                const float a = As[ry*4 + i][kk];
                const ull aa = pack2(a, a);
                acc2[i][0] = fma2(aa, bb0, acc2[i][0]);
                acc2[i][1] = fma2(aa, bb1, acc2[i][1]);
            }
        }
        __syncthreads();
    }
    const float4 bv4 = *(const float4*)(bias + n0 + rx*4);
#pragma unroll
    for (int i = 0; i < 4; i++) {
        const int m = m0 + ry*4 + i;
        if (m >= M) continue;
        float r0, r1, r2, r3;
        unpack2(acc2[i][0], r0, r1);
        unpack2(acc2[i][1], r2, r3);
        float4 o = make_float4(r0 + bv4.x, r1 + bv4.y, r2 + bv4.z, r3 + bv4.w);
        *(float4*)(C + (size_t)m * CH + n0 + rx*4) = o;
    }
}

// ---------------------------------------------------------------------------
// 4) Attention: one thread per query, per (b,h). Packed f32x2 math:
//    16 FFMA2 (score) + 16 FFMA2 (o update) + 1 exp per key.
// ---------------------------------------------------------------------------
__global__ __launch_bounds__(128)
void attn_kernel(const float* __restrict__ Qp,
                 const float* __restrict__ Kp,
                 const float* __restrict__ Vp,
                 float* __restrict__ Out) {
    const int pair = blockIdx.x;
    const int b = pair >> 3, h = pair & 7;
    const int tid = threadIdx.x;
    const int qi = blockIdx.y * 128 + tid;
    const bool active = (qi < NQ);

    __shared__ float2 ks2[64][16];
    __shared__ float2 vs2[64][16];

    ull qq[16];
    if (active) {
        const float2* qp = (const float2*)(Qp + ((size_t)b*NQ + qi)*CH + h*HD);
#pragma unroll
        for (int i = 0; i < 16; i++) {
            float2 v = qp[i];
            qq[i] = pack2(v.x * 0.1767766953f, v.y * 0.1767766953f);
        }
    }
    float m = -1e30f, l = 0.f;
    ull oo[16];
#pragma unroll
    for (int i = 0; i < 16; i++) oo[i] = 0ull;

    for (int kt = 0; kt < NQ; kt += 64) {
        const int cnt = min(64, NQ - kt);
        __syncthreads();
        for (int idx = tid; idx < 64*16; idx += 128) {
            const int r = idx >> 4, d2 = idx & 15;
            if (r < cnt) {
                const size_t off = ((size_t)b*NQ + kt + r)*CH + h*HD;
                ks2[r][d2] = *(const float2*)(Kp + off + 2*d2);
                vs2[r][d2] = *(const float2*)(Vp + off + 2*d2);
            }
        }
        __syncthreads();
        if (active) {
            for (int j = 0; j < cnt; j++) {
                ull s0 = 0ull, s1 = 0ull, s2 = 0ull, s3 = 0ull;
                const ull* krow = (const ull*)&ks2[j][0];
#pragma unroll
                for (int i = 0; i < 16; i += 4) {
                    s0 = fma2(qq[i+0], krow[i+0], s0);
                    s1 = fma2(qq[i+1], krow[i+1], s1);
                    s2 = fma2(qq[i+2], krow[i+2], s2);
                    s3 = fma2(qq[i+3], krow[i+3], s3);
                }
                float a0, a1, b0c, b1c, c0c, c1c, d0, d1;
                unpack2(s0, a0, a1); unpack2(s1, b0c, b1c);
                unpack2(s2, c0c, c1c); unpack2(s3, d0, d1);
                const float s = ((a0 + a1) + (b0c + b1c)) + ((c0c + c1c) + (d0 + d1));
                const ull* vrow = (const ull*)&vs2[j][0];
                if (s > m) {
                    const float r = __expf(m - s);
                    const ull rr = pack2(r, r);
                    l = l * r + 1.f;
#pragma unroll
                    for (int i = 0; i < 16; i++) oo[i] = fma2(oo[i], rr, vrow[i]);
                    m = s;
                } else {
                    const float p = __expf(s - m);
                    const ull pp = pack2(p, p);
                    l += p;
#pragma unroll
                    for (int i = 0; i < 16; i++) oo[i] = fma2(pp, vrow[i], oo[i]);
                }
            }
        }
    }
    if (active) {
        const float inv = 1.f / l;
        float2* op = (float2*)(Out + ((size_t)b*NQ + qi)*CH + h*HD);
#pragma unroll
        for (int i = 0; i < 16; i++) {
            float lo, hi; unpack2(oo[i], lo, hi);
            op[i] = make_float2(lo * inv, hi * inv);
        }
    }
}

// ---------------------------------------------------------------------------
// Launch
// ---------------------------------------------------------------------------
extern "C" void kernel_launch(void* const* d_in, const int* in_sizes, int n_in,
                              void* d_out, int out_size) {
    (void)in_sizes; (void)n_in; (void)out_size;
    const float* f0   = (const float*)d_in[0];
    const float* f1   = (const float*)d_in[1];
    const float* refs = (const float*)d_in[2];
    const float* intr = (const float*)d_in[3];
    const float* extr = (const float*)d_in[4];
    const float* qin  = (const float*)d_in[5];
    const float* Wq = (const float*)d_in[6];  const float* bq = (const float*)d_in[7];
    const float* Wk = (const float*)d_in[8];  const float* bk = (const float*)d_in[9];
    const float* Wv = (const float*)d_in[10]; const float* bv = (const float*)d_in[11];
    const float* Wo = (const float*)d_in[12]; const float* bo = (const float*)d_in[13];

    __half* feat;
    float*  mats;
    cudaGetSymbolAddress((void**)&feat, g_feat);
    cudaGetSymbolAddress((void**)&mats, g_mats);
    __half* pf0t = feat;
    __half* pf1t = feat + N_F0T;
    float* pctx = mats;
    float* pq   = pctx + N_MAT;
    float* pk   = pq   + N_MAT;
    float* pv   = pk   + N_MAT;
    float* pao  = pv   + N_MAT;

    // 1) channel-last fp16 transpose of both feature levels
    transpose_f16<<<dim3(HW0/32, CH/32, BATCH*VIEWS), dim3(32, 8)>>>(f0, pf0t, HW0);
    transpose_f16<<<dim3(HW1/32, CH/32, BATCH*VIEWS), dim3(32, 8)>>>(f1, pf1t, HW1);

    // 2) multi-view sampler -> ctx [B,Q,C]
    sampler_kernel<<<BATCH*NQ, 128>>>(refs, intr, extr, pf0t, pf1t, pctx);

    // 3) Q/K/V projections — one batched launch (grid.z = 3)
    const int M = BATCH * NQ;                       // 1800
    dim3 g3(CH/GBN, (M + GBM - 1)/GBM, 3);
    gemm_nt3<<<g3, 256>>>(qin, pctx, pctx,
                          Wq, Wk, Wv,
                          bq, bk, bv,
                          pq, pk, pv, M);

    // 4) attention
    attn_kernel<<<dim3(BATCH*NHEAD, (NQ + 127)/128), 128>>>(pq, pk, pv, pao);

    // 5) output projection -> d_out
    dim3 g1(CH/GBN, (M + GBM - 1)/GBM, 1);
    gemm_nt3<<<g1, 256>>>(pao, pao, pao,
                          Wo, Wo, Wo,
                          bo, bo, bo,
                          (float*)d_out, (float*)d_out, (float*)d_out, M);
}

// round 11
// speedup vs baseline: 1.3709x; 1.2658x over previous
#include <cuda_runtime.h>
#include <cuda_fp16.h>
#include <math.h>

// Problem constants
#define BATCH 2
#define VIEWS 6
#define CH    256
#define NQ    900
#define H0    64
#define W0    176
#define H1    32
#define W1    88
#define HW0   (H0*W0)     // 11264
#define HW1   (H1*W1)     // 2816
#define NHEAD 8
#define HD    32
#define KSPLIT 2
#define KHALF (NQ/KSPLIT)   // 450
#define NBHQ  (BATCH*NHEAD*NQ)  // 14400

typedef unsigned long long ull;

// packed f32x2 helpers (FFMA2 — only reachable via PTX fma.rn.f32x2)
__device__ __forceinline__ ull pack2(float lo, float hi) {
    ull r; asm("mov.b64 %0,{%1,%2};" : "=l"(r) : "f"(lo), "f"(hi)); return r;
}
__device__ __forceinline__ void unpack2(ull v, float& lo, float& hi) {
    asm("mov.b64 {%0,%1},%2;" : "=f"(lo), "=f"(hi) : "l"(v));
}
__device__ __forceinline__ ull fma2(ull a, ull b, ull c) {
    ull d; asm("fma.rn.f32x2 %0,%1,%2,%3;" : "=l"(d) : "l"(a), "l"(b), "l"(c)); return d;
}

// ---------------------------------------------------------------------------
// Scratch (static device globals; allocation-free per harness rules)
// ---------------------------------------------------------------------------
#define N_F0T ((size_t)BATCH*VIEWS*HW0*CH)   // 34,603,008
#define N_F1T ((size_t)BATCH*VIEWS*HW1*CH)   //  8,650,752
#define N_MAT ((size_t)BATCH*NQ*CH)          //    460,800
__device__ __align__(256) __half g_feat[N_F0T + N_F1T];   // fp16 channel-last features
__device__ __align__(256) float  g_mats[5*N_MAT];         // ctx | q | k | v | ao
__device__ __align__(256) float  g_pm[KSPLIT*NBHQ];       // split-K partial max
__device__ __align__(256) float  g_pl[KSPLIT*NBHQ];       // split-K partial sum
__device__ __align__(256) float  g_po[(size_t)KSPLIT*NBHQ*HD]; // split-K partial out

// ---------------------------------------------------------------------------
// 1) Transpose [C,HW] -> [HW,C] per (b,v), fp32 -> fp16
// ---------------------------------------------------------------------------
__global__ __launch_bounds__(256)
void transpose_f16(const float* __restrict__ in, __half* __restrict__ out, int HW) {
    __shared__ float tile[32][33];      // [c][p]
    const int bv = blockIdx.z;
    const int p0 = blockIdx.x * 32;
    const int c0 = blockIdx.y * 32;
    const float* src = in  + (size_t)bv * CH * HW;
    __half*      dst = out + (size_t)bv * HW * CH;
    const int tx = threadIdx.x, ty = threadIdx.y;   // 32 x 8
#pragma unroll
    for (int i = 0; i < 32; i += 8)
        tile[ty + i][tx] = src[(size_t)(c0 + ty + i) * HW + (p0 + tx)];
    __syncthreads();
    const int tid = ty * 32 + tx;
#pragma unroll
    for (int i = 0; i < 2; i++) {
        const int idx = tid + i * 256;       // 0..511
        const int p = idx >> 4, c2 = idx & 15;
        __half2 h = __floats2half2_rn(tile[2*c2][p], tile[2*c2 + 1][p]);
        *(__half2*)(dst + (size_t)(p0 + p) * CH + c0 + 2*c2) = h;
    }
}

// ---------------------------------------------------------------------------
// 2) Sampler: one block per (b,q); 128 threads, 2 channels per thread (half2).
// ---------------------------------------------------------------------------
__global__ __launch_bounds__(128)
void sampler_kernel(const float* __restrict__ refs,
                    const float* __restrict__ intr,
                    const float* __restrict__ extr,
                    const __half* __restrict__ f0t,
                    const __half* __restrict__ f1t,
                    float* __restrict__ ctx) {
    const int b = blockIdx.x / NQ;
    const int q = blockIdx.x % NQ;
    const int t = threadIdx.x;           // channel pair 0..127

    __shared__ float sx[2][24], sy[2][24];
    __shared__ int   sval[24];

    if (t < 24) {
        const int v = t >> 2, k = t & 3;
        const float kx[4] = {0.f, 2.f, 0.f, -2.f};
        const float ky[4] = {0.f, 0.f, 2.f,  0.f};
        const float px = refs[((size_t)b*NQ + q)*3 + 0] + kx[k];
        const float py = refs[((size_t)b*NQ + q)*3 + 1] + ky[k];
        const float pz = refs[((size_t)b*NQ + q)*3 + 2];
        const float* E  = extr + (size_t)(b*VIEWS + v)*16;
        const float* Kk = intr + (size_t)(b*VIEWS + v)*9;
        const float c0 = E[0]*px + E[1]*py + E[2]*pz  + E[3];
        const float c1 = E[4]*px + E[5]*py + E[6]*pz  + E[7];
        const float c2 = E[8]*px + E[9]*py + E[10]*pz + E[11];
        const float uu = Kk[0]*c0 + Kk[1]*c1 + Kk[2]*c2;
        const float vv = Kk[3]*c0 + Kk[4]*c1 + Kk[5]*c2;
        const float zz = Kk[6]*c0 + Kk[7]*c1 + Kk[8]*c2;
        const float zs = (fabsf(zz) > 1e-6f) ? zz : 1e-6f;
        const float iu = uu / zs, iv = vv / zs;
        {   // replicate reference grid round-trip exactly
            float gx = 2.f * iu / (float)(W0 - 1) - 1.f;
            float gy = 2.f * iv / (float)(H0 - 1) - 1.f;
            sx[0][t] = (gx + 1.f) * 0.5f * (float)(W0 - 1);
            sy[0][t] = (gy + 1.f) * 0.5f * (float)(H0 - 1);
        }
        {
            float gx = 2.f * iu / (float)(W1 - 1) - 1.f;
            float gy = 2.f * iv / (float)(H1 - 1) - 1.f;
            sx[1][t] = (gx + 1.f) * 0.5f * (float)(W1 - 1);
            sy[1][t] = (gy + 1.f) * 0.5f * (float)(H1 - 1);
        }
        sval[t] = (zz > 0.f) ? 1 : 0;
    }
    __syncthreads();

    float cnt = 0.f;
#pragma unroll
    for (int i = 0; i < 24; i++) cnt += (float)sval[i];
    cnt = fmaxf(cnt, 1.f);

    float ax = 0.f, ay = 0.f;
    for (int i = 0; i < 24; i++) {
        if (!sval[i]) continue;
        const int v = i >> 2;
#pragma unroll
        for (int l = 0; l < 2; l++) {
            const int W = l ? W1 : W0;
            const int H = l ? H1 : H0;
            const __half2* base2 = (const __half2*)(l
                ? (f1t + (size_t)(b*VIEWS + v)*HW1*CH)
                : (f0t + (size_t)(b*VIEWS + v)*HW0*CH));
            const float x = sx[l][i], y = sy[l][i];
            const float x0f = floorf(x), y0f = floorf(y);
            const float wx1 = x - x0f, wx0 = 1.f - wx1;
            const float wy1 = y - y0f, wy0 = 1.f - wy1;
#pragma unroll
            for (int dy = 0; dy < 2; dy++) {
#pragma unroll
                for (int dx = 0; dx < 2; dx++) {
                    const float xf = x0f + (float)dx;
                    const float yf = y0f + (float)dy;
                    if (xf >= 0.f && xf <= (float)(W - 1) &&
                        yf >= 0.f && yf <= (float)(H - 1)) {
                        const int xi = (int)xf, yi = (int)yf;
                        const float w = (dx ? wx1 : wx0) * (dy ? wy1 : wy0);
                        float2 f = __half22float2(base2[(size_t)(yi * W + xi)*(CH/2) + t]);
                        ax = fmaf(w, f.x, ax);
                        ay = fmaf(w, f.y, ay);
                    }
                }
            }
        }
    }
    const float inv = 1.f / (2.f * cnt);
    float2 outv = make_float2(ax * inv, ay * inv);
    *(float2*)(ctx + ((size_t)b*NQ + q)*CH + 2*t) = outv;
}

// ---------------------------------------------------------------------------
// 3) GEMM (NT) with z-batching + packed f32x2 inner product.
// ---------------------------------------------------------------------------
#define GBM 64
#define GBN 64
#define GBK 16
__global__ __launch_bounds__(256)
void gemm_nt3(const float* __restrict__ A0, const float* __restrict__ A1, const float* __restrict__ A2,
              const float* __restrict__ W0p, const float* __restrict__ W1p, const float* __restrict__ W2p,
              const float* __restrict__ b0, const float* __restrict__ b1, const float* __restrict__ b2,
              float* __restrict__ C0, float* __restrict__ C1, float* __restrict__ C2, int M) {
    const int z = blockIdx.z;
    const float* A    = (z == 0) ? A0 : (z == 1) ? A1 : A2;
    const float* Wt   = (z == 0) ? W0p : (z == 1) ? W1p : W2p;
    const float* bias = (z == 0) ? b0 : (z == 1) ? b1 : b2;
    float*       C    = (z == 0) ? C0 : (z == 1) ? C1 : C2;

    __shared__ float As[GBM][GBK + 1];   // [m][k]
    __shared__ float Bs[GBK][GBN + 2];   // [k][n]
    const int tid = threadIdx.x;
    const int m0 = blockIdx.y * GBM, n0 = blockIdx.x * GBN;
    const int lr = tid >> 2;           // 0..63
    const int lc = (tid & 3) * 4;      // 0,4,8,12
    const int ry = tid >> 4;           // 0..15 (m sub-tile)
    const int rx = tid & 15;           // 0..15 (n sub-tile)

    ull acc2[4][2];
#pragma unroll
    for (int i = 0; i < 4; i++) { acc2[i][0] = 0ull; acc2[i][1] = 0ull; }

    for (int k0 = 0; k0 < CH; k0 += GBK) {
        const int am = m0 + lr;
        float4 av = make_float4(0.f, 0.f, 0.f, 0.f);
        if (am < M) av = *(const float4*)(A + (size_t)am * CH + k0 + lc);
        As[lr][lc+0] = av.x; As[lr][lc+1] = av.y;
        As[lr][lc+2] = av.z; As[lr][lc+3] = av.w;
        float4 wv = *(const float4*)(Wt + (size_t)(n0 + lr) * CH + k0 + lc);
        Bs[lc+0][lr] = wv.x; Bs[lc+1][lr] = wv.y;
        Bs[lc+2][lr] = wv.z; Bs[lc+3][lr] = wv.w;
        __syncthreads();
#pragma unroll
        for (int kk = 0; kk < GBK; kk++) {
            const ull bb0 = *(const ull*)&Bs[kk][rx*4];
            const ull bb1 = *(const ull*)&Bs[kk][rx*4 + 2];
#pragma unroll
            for (int i = 0; i < 4; i++) {
                const float a = As[ry*4 + i][kk];
                const ull aa = pack2(a, a);
                acc2[i][0] = fma2(aa, bb0, acc2[i][0]);
                acc2[i][1] = fma2(aa, bb1, acc2[i][1]);
            }
        }
        __syncthreads();
    }
    const float4 bv4 = *(const float4*)(bias + n0 + rx*4);
#pragma unroll
    for (int i = 0; i < 4; i++) {
        const int m = m0 + ry*4 + i;
        if (m >= M) continue;
        float r0, r1, r2, r3;
        unpack2(acc2[i][0], r0, r1);
        unpack2(acc2[i][1], r2, r3);
        float4 o = make_float4(r0 + bv4.x, r1 + bv4.y, r2 + bv4.z, r3 + bv4.w);
        *(float4*)(C + (size_t)m * CH + n0 + rx*4) = o;
    }
}

// ---------------------------------------------------------------------------
// 4a) Attention split-K: grid (b*h, qtile, split). Each split handles 450 keys,
//     writes partial (m, l, unnormalized o).
// ---------------------------------------------------------------------------
__global__ __launch_bounds__(128)
void attn_split_kernel(const float* __restrict__ Qp,
                       const float* __restrict__ Kp,
                       const float* __restrict__ Vp,
                       float* __restrict__ Pm, float* __restrict__ Pl,
                       float* __restrict__ Po) {
    const int pair = blockIdx.x;
    const int b = pair >> 3, h = pair & 7;
    const int z = blockIdx.z;
    const int tid = threadIdx.x;
    const int qi = blockIdx.y * 128 + tid;
    const bool active = (qi < NQ);

    __shared__ float2 ks2[64][16];
    __shared__ float2 vs2[64][16];

    ull qq[16];
    if (active) {
        const float2* qp = (const float2*)(Qp + ((size_t)b*NQ + qi)*CH + h*HD);
#pragma unroll
        for (int i = 0; i < 16; i++) {
            float2 v = qp[i];
            qq[i] = pack2(v.x * 0.1767766953f, v.y * 0.1767766953f);
        }
    }
    float m = -1e30f, l = 0.f;
    ull oo[16];
#pragma unroll
    for (int i = 0; i < 16; i++) oo[i] = 0ull;

    const int kbase = z * KHALF;
    for (int kt = 0; kt < KHALF; kt += 64) {
        const int cnt = min(64, KHALF - kt);
        __syncthreads();
        for (int idx = tid; idx < 64*16; idx += 128) {
            const int r = idx >> 4, d2 = idx & 15;
            if (r < cnt) {
                const size_t off = ((size_t)b*NQ + kbase + kt + r)*CH + h*HD;
                ks2[r][d2] = *(const float2*)(Kp + off + 2*d2);
                vs2[r][d2] = *(const float2*)(Vp + off + 2*d2);
            }
        }
        __syncthreads();
        if (active) {
            for (int j = 0; j < cnt; j++) {
                ull s0 = 0ull, s1 = 0ull, s2 = 0ull, s3 = 0ull;
                const ull* krow = (const ull*)&ks2[j][0];
#pragma unroll
                for (int i = 0; i < 16; i += 4) {
                    s0 = fma2(qq[i+0], krow[i+0], s0);
                    s1 = fma2(qq[i+1], krow[i+1], s1);
                    s2 = fma2(qq[i+2], krow[i+2], s2);
                    s3 = fma2(qq[i+3], krow[i+3], s3);
                }
                float a0, a1, b0c, b1c, c0c, c1c, d0, d1;
                unpack2(s0, a0, a1); unpack2(s1, b0c, b1c);
                unpack2(s2, c0c, c1c); unpack2(s3, d0, d1);
                const float s = ((a0 + a1) + (b0c + b1c)) + ((c0c + c1c) + (d0 + d1));
                const ull* vrow = (const ull*)&vs2[j][0];
                if (s > m) {
                    const float r = __expf(m - s);
                    const ull rr = pack2(r, r);
                    l = l * r + 1.f;
#pragma unroll
                    for (int i = 0; i < 16; i++) oo[i] = fma2(oo[i], rr, vrow[i]);
                    m = s;
                } else {
                    const float p = __expf(s - m);
                    const ull pp = pack2(p, p);
                    l += p;
#pragma unroll
                    for (int i = 0; i < 16; i++) oo[i] = fma2(pp, vrow[i], oo[i]);
                }
            }
        }
    }
    if (active) {
        const size_t idx = (size_t)(b*NHEAD + h)*NQ + qi;      // 0..14399
        const size_t part = (size_t)z*NBHQ + idx;
        Pm[part] = m;
        Pl[part] = l;
        float2* po = (float2*)(Po + part*HD);
#pragma unroll
        for (int i = 0; i < 16; i++) {
            float lo, hi; unpack2(oo[i], lo, hi);
            po[i] = make_float2(lo, hi);
        }
    }
}

// ---------------------------------------------------------------------------
// 4b) Split-K merge: combine 2 partials per (b,h,q). One query per warp.
// ---------------------------------------------------------------------------
__global__ __launch_bounds__(128)
void attn_merge_kernel(const float* __restrict__ Pm, const float* __restrict__ Pl,
                       const float* __restrict__ Po, float* __restrict__ Out) {
    const int g = blockIdx.x * 4 + (threadIdx.x >> 5);   // query idx 0..14399
    const int d = threadIdx.x & 31;
    if (g >= NBHQ) return;
    const float m0 = Pm[g], l0 = Pl[g];
    const float m1 = Pm[NBHQ + g], l1 = Pl[NBHQ + g];
    const float M = fmaxf(m0, m1);
    const float w0 = __expf(m0 - M), w1 = __expf(m1 - M);
    const float L = l0 * w0 + l1 * w1;
    const float invL = 1.f / L;
    const float o0 = Po[(size_t)g*HD + d];
    const float o1 = Po[(size_t)(NBHQ + g)*HD + d];
    const float o = (o0 * w0 + o1 * w1) * invL;
    const int b = g / (NHEAD*NQ);
    const int h = (g / NQ) % NHEAD;
    const int qi = g % NQ;
    Out[((size_t)b*NQ + qi)*CH + h*HD + d] = o;
}

// ---------------------------------------------------------------------------
// Launch
// ---------------------------------------------------------------------------
extern "C" void kernel_launch(void* const* d_in, const int* in_sizes, int n_in,
                              void* d_out, int out_size) {
    (void)in_sizes; (void)n_in; (void)out_size;
    const float* f0   = (const float*)d_in[0];
    const float* f1   = (const float*)d_in[1];
    const float* refs = (const float*)d_in[2];
    const float* intr = (const float*)d_in[3];
    const float* extr = (const float*)d_in[4];
    const float* qin  = (const float*)d_in[5];
    const float* Wq = (const float*)d_in[6];  const float* bq = (const float*)d_in[7];
    const float* Wk = (const float*)d_in[8];  const float* bk = (const float*)d_in[9];
    const float* Wv = (const float*)d_in[10]; const float* bv = (const float*)d_in[11];
    const float* Wo = (const float*)d_in[12]; const float* bo = (const float*)d_in[13];

    __half* feat;
    float *mats, *pm, *pl, *po;
    cudaGetSymbolAddress((void**)&feat, g_feat);
    cudaGetSymbolAddress((void**)&mats, g_mats);
    cudaGetSymbolAddress((void**)&pm,   g_pm);
    cudaGetSymbolAddress((void**)&pl,   g_pl);
    cudaGetSymbolAddress((void**)&po,   g_po);
    __half* pf0t = feat;
    __half* pf1t = feat + N_F0T;
    float* pctx = mats;
    float* pq   = pctx + N_MAT;
    float* pk   = pq   + N_MAT;
    float* pv   = pk   + N_MAT;
    float* pao  = pv   + N_MAT;

    // 1) channel-last fp16 transpose of both feature levels
    transpose_f16<<<dim3(HW0/32, CH/32, BATCH*VIEWS), dim3(32, 8)>>>(f0, pf0t, HW0);
    transpose_f16<<<dim3(HW1/32, CH/32, BATCH*VIEWS), dim3(32, 8)>>>(f1, pf1t, HW1);

    // 2) multi-view sampler -> ctx [B,Q,C]
    sampler_kernel<<<BATCH*NQ, 128>>>(refs, intr, extr, pf0t, pf1t, pctx);

    // 3) Q/K/V projections — one batched launch (grid.z = 3)
    const int M = BATCH * NQ;                       // 1800
    dim3 g3(CH/GBN, (M + GBM - 1)/GBM, 3);
    gemm_nt3<<<g3, 256>>>(qin, pctx, pctx,
                          Wq, Wk, Wv,
                          bq, bk, bv,
                          pq, pk, pv, M);

    // 4) attention: 2-way split-K + merge
    attn_split_kernel<<<dim3(BATCH*NHEAD, (NQ + 127)/128, KSPLIT), 128>>>(pq, pk, pv, pm, pl, po);
    attn_merge_kernel<<<(NBHQ + 3)/4, 128>>>(pm, pl, po, pao);

    // 5) output projection -> d_out
    dim3 g1(CH/GBN, (M + GBM - 1)/GBM, 1);
    gemm_nt3<<<g1, 256>>>(pao, pao, pao,
                          Wo, Wo, Wo,
                          bo, bo, bo,
                          (float*)d_out, (float*)d_out, (float*)d_out, M);
}